// round 1
// baseline (speedup 1.0000x reference)
#include <cuda_runtime.h>
#include <cuda_bf16.h>

// ---------------------------------------------------------------------------
// SparseGATv2Layer: N=50000 nodes, IN=128, H=4 heads, C=32, E=800000 edges.
// Pipeline:
//   proj = x @ W_lin^T            (GEMM 1)
//   out  = x @ W_res^T + bias     (GEMM 2, residual written directly to d_out)
//   per edge (incl. self loops): logits[e,h] = sum_c leaky(ps+pd)*att + red*W_eb
//   segment softmax over dst, msg = attn * ps, segment-sum into out.
// ---------------------------------------------------------------------------

#define MAXN 50000
#define MAXE 800000
#define MAXET (MAXE + MAXN)

__device__ float    g_proj[MAXN * 128];   // 25.6 MB  (fits L2)
__device__ float    g_elog[MAXET * 4];    // 13.6 MB  logits, then reused as exp values
__device__ unsigned g_mx[MAXN * 4];       // ordered-uint encoded segment max
__device__ float    g_den[MAXN * 4];      // softmax denominators
__device__ int      g_idx64;              // 1 if edge_index is int64, 0 if int32

// ---- ordered-uint encoding for float atomicMax --------------------------------
__device__ __forceinline__ unsigned f2ord(float f) {
    unsigned u = __float_as_uint(f);
    return u ^ ((unsigned)((int)u >> 31) | 0x80000000u);
}
__device__ __forceinline__ float ord2f(unsigned v) {
    unsigned u = (v & 0x80000000u) ? (v ^ 0x80000000u) : ~v;
    return __uint_as_float(u);
}

// ---- edge-index accessor: handles int64 OR int32 serialization ----------------
__device__ __forceinline__ int load_idx(const void* ei, int i) {
    if (g_idx64)
        return (int)((const long long*)ei)[i];
    else
        return ((const int*)ei)[i];
}

// ================================================================================
// init: zero segment buffers, assume int64 until probe says otherwise
// ================================================================================
__global__ void init_kernel(int n4) {
    int i = blockIdx.x * blockDim.x + threadIdx.x;
    if (i == 0) g_idx64 = 1;
    if (i < n4) { g_mx[i] = 0u; g_den[i] = 0.0f; }
}

// Probe: interpret first `cnt` 8-byte words as int64. If edge_index is really
// int32, these are (lo,hi) pairs of random node ids -> virtually all >= N.
__global__ void detect_kernel(const long long* ei, int cnt, int N) {
    int i = blockIdx.x * blockDim.x + threadIdx.x;
    if (i >= cnt) return;
    long long v = ei[i];
    if (v < 0 || v >= (long long)N) g_idx64 = 0;
}

// ================================================================================
// Fused dual GEMM: grid.y==0 -> proj = x @ W_lin^T
//                  grid.y==1 -> out  = x @ W_res^T + bias
// 128x128 block tile, K chunked by 32, 8x8 micro-tile per thread (256 threads).
// ================================================================================
__global__ __launch_bounds__(256, 2) void gemm_kernel(
    const float* __restrict__ x, const float* __restrict__ W_lin,
    const float* __restrict__ W_res, const float* __restrict__ bias,
    float* __restrict__ out, int N)
{
    __shared__ float xs[32][132];   // [k][row]   16.9 KB
    __shared__ float ws[32][132];   // [k][tcol]  16.9 KB

    const int tid = threadIdx.x;
    const int tx = tid & 15;        // col group (8 cols)
    const int ty = tid >> 4;        // row group (8 rows)
    const int rbase = blockIdx.x * 128;
    const float* W = (blockIdx.y == 0) ? W_lin : W_res;

    float acc[8][8];
#pragma unroll
    for (int i = 0; i < 8; i++)
#pragma unroll
        for (int j = 0; j < 8; j++) acc[i][j] = 0.0f;

    for (int kb = 0; kb < 128; kb += 32) {
#pragma unroll
        for (int li = tid; li < 32 * 128; li += 256) {
            int r = li >> 5;          // row / weight-row
            int k = li & 31;
            int row = rbase + r;
            xs[k][r] = (row < N) ? x[row * 128 + kb + k] : 0.0f;
            ws[k][r] = W[r * 128 + kb + k];
        }
        __syncthreads();
#pragma unroll
        for (int k = 0; k < 32; k++) {
            float a[8], b[8];
            *(float4*)&a[0] = *(const float4*)&xs[k][ty * 8];
            *(float4*)&a[4] = *(const float4*)&xs[k][ty * 8 + 4];
            *(float4*)&b[0] = *(const float4*)&ws[k][tx * 8];
            *(float4*)&b[4] = *(const float4*)&ws[k][tx * 8 + 4];
#pragma unroll
            for (int i = 0; i < 8; i++)
#pragma unroll
                for (int j = 0; j < 8; j++)
                    acc[i][j] = fmaf(a[i], b[j], acc[i][j]);
        }
        __syncthreads();
    }

    const int col = tx * 8;
#pragma unroll
    for (int i = 0; i < 8; i++) {
        int row = rbase + ty * 8 + i;
        if (row >= N) break;
        if (blockIdx.y == 0) {
            float4 v0 = make_float4(acc[i][0], acc[i][1], acc[i][2], acc[i][3]);
            float4 v1 = make_float4(acc[i][4], acc[i][5], acc[i][6], acc[i][7]);
            *(float4*)&g_proj[row * 128 + col]     = v0;
            *(float4*)&g_proj[row * 128 + col + 4] = v1;
        } else {
            float4 v0, v1;
            v0.x = acc[i][0] + bias[col + 0];
            v0.y = acc[i][1] + bias[col + 1];
            v0.z = acc[i][2] + bias[col + 2];
            v0.w = acc[i][3] + bias[col + 3];
            v1.x = acc[i][4] + bias[col + 4];
            v1.y = acc[i][5] + bias[col + 5];
            v1.z = acc[i][6] + bias[col + 6];
            v1.w = acc[i][7] + bias[col + 7];
            *(float4*)&out[row * 128 + col]     = v0;
            *(float4*)&out[row * 128 + col + 4] = v1;
        }
    }
}

// ================================================================================
// Pass A: one warp per edge. Gather proj[src], proj[dst] (float4/lane),
// compute logits[e,h] for h=0..3, store, and segment-max into g_mx.
// Lane l covers elements 4l..4l+3 => head h = l>>3 (constant within 8-lane group).
// ================================================================================
__global__ void edge_logits_kernel(const void* __restrict__ ei,
                                   const float* __restrict__ ea,
                                   const float* __restrict__ att,
                                   const float* __restrict__ W_eb,
                                   int E, int N)
{
    int w = (blockIdx.x * blockDim.x + threadIdx.x) >> 5;
    int lane = threadIdx.x & 31;
    int Et = E + N;
    if (w >= Et) return;

    int src, dst;
    float red;
    if (w < E) {
        src = load_idx(ei, w);
        dst = load_idx(ei, E + w);
        float2 e2 = ((const float2*)ea)[w];
        red = e2.x + 0.35f * e2.y;
    } else {
        src = dst = w - E;
        red = 1.0f;
    }

    const float4* p4 = (const float4*)g_proj;
    float4 ps = p4[src * 32 + lane];
    float4 pd = p4[dst * 32 + lane];
    float4 a4 = ((const float4*)att)[lane];

    float zx = ps.x + pd.x; zx = fmaxf(zx, 0.2f * zx);
    float zy = ps.y + pd.y; zy = fmaxf(zy, 0.2f * zy);
    float zz = ps.z + pd.z; zz = fmaxf(zz, 0.2f * zz);
    float zw = ps.w + pd.w; zw = fmaxf(zw, 0.2f * zw);

    float part = zx * a4.x + zy * a4.y + zz * a4.z + zw * a4.w;
    part += __shfl_xor_sync(0xffffffffu, part, 4);
    part += __shfl_xor_sync(0xffffffffu, part, 2);
    part += __shfl_xor_sync(0xffffffffu, part, 1);

    if ((lane & 7) == 0) {
        int h = lane >> 3;
        float logit = part + red * __ldg(&W_eb[h]);
        g_elog[w * 4 + h] = logit;
        atomicMax(&g_mx[dst * 4 + h], f2ord(logit));
    }
}

// ================================================================================
// Pass B: one thread per (edge, head). e = exp(logit - max[dst]); segment-sum.
// g_elog is overwritten in place with the exp values.
// ================================================================================
__global__ void edge_exp_kernel(const void* __restrict__ ei, int E, int N)
{
    int i = blockIdx.x * blockDim.x + threadIdx.x;
    int total = (E + N) * 4;
    if (i >= total) return;
    int e = i >> 2;
    int h = i & 3;
    int dst = (e < E) ? load_idx(ei, E + e) : (e - E);
    float v = expf(g_elog[i] - ord2f(g_mx[dst * 4 + h]));
    g_elog[i] = v;
    atomicAdd(&g_den[dst * 4 + h], v);
}

// ================================================================================
// Pass C: one warp per edge. attn = exp/denom; scatter attn*proj[src] into
// out[dst] with one vectorized red.global.add.v4.f32 per lane.
// ================================================================================
__global__ void edge_aggr_kernel(const void* __restrict__ ei,
                                 float* __restrict__ out, int E, int N)
{
    int w = (blockIdx.x * blockDim.x + threadIdx.x) >> 5;
    int lane = threadIdx.x & 31;
    int Et = E + N;
    if (w >= Et) return;

    int src, dst;
    if (w < E) {
        src = load_idx(ei, w);
        dst = load_idx(ei, E + w);
    } else {
        src = dst = w - E;
    }

    int h = lane >> 3;
    float attn = g_elog[w * 4 + h] / fmaxf(g_den[dst * 4 + h], 1e-12f);
    float4 ps = ((const float4*)g_proj)[src * 32 + lane];

    float mx = attn * ps.x;
    float my = attn * ps.y;
    float mz = attn * ps.z;
    float mw = attn * ps.w;

    float* addr = out + dst * 128 + lane * 4;
    asm volatile("red.global.add.v4.f32 [%0], {%1, %2, %3, %4};"
                 :: "l"(addr), "f"(mx), "f"(my), "f"(mz), "f"(mw)
                 : "memory");
}

// ================================================================================
// Launch
// ================================================================================
extern "C" void kernel_launch(void* const* d_in, const int* in_sizes, int n_in,
                              void* d_out, int out_size)
{
    const float*     x     = (const float*)d_in[0];
    const void*      ei    = (const void*)d_in[1];   // int64 or int32, probed on device
    const float*     ea    = (const float*)d_in[2];
    const float*     W_lin = (const float*)d_in[3];
    const float*     att   = (const float*)d_in[4];
    const float*     W_eb  = (const float*)d_in[5];
    const float*     bias  = (const float*)d_in[6];
    const float*     W_res = (const float*)d_in[7];
    float* out = (float*)d_out;

    int N  = in_sizes[0] / 128;
    int E  = in_sizes[1] / 2;
    int Et = E + N;

    init_kernel<<<(N * 4 + 255) / 256, 256>>>(N * 4);

    // dtype probe: read first min(E, 65536) 8-byte words (safe for both layouts)
    int probe = (E < 65536) ? E : 65536;
    detect_kernel<<<(probe + 255) / 256, 256>>>((const long long*)ei, probe, N);

    gemm_kernel<<<dim3((N + 127) / 128, 2), 256>>>(x, W_lin, W_res, bias, out, N);

    int blocksW = (Et * 32 + 255) / 256;   // one warp per edge
    edge_logits_kernel<<<blocksW, 256>>>(ei, ea, att, W_eb, E, N);
    edge_exp_kernel<<<(Et * 4 + 255) / 256, 256>>>(ei, E, N);
    edge_aggr_kernel<<<blocksW, 256>>>(ei, out, E, N);
}

// round 2
// speedup vs baseline: 1.4686x; 1.4686x over previous
#include <cuda_runtime.h>
#include <cuda_bf16.h>

// ---------------------------------------------------------------------------
// SparseGATv2Layer, edge-sorted formulation.
//   1. proj = x @ W_lin^T ; res = x @ W_res^T + bias  (written to d_out)
//   2. counting-sort edges (incl. self loops) by dst
//   3. one warp per dst node: logits -> max -> exp -> denom -> weighted
//      aggregation, all segment state in registers, no atomics.
// ---------------------------------------------------------------------------

#define MAXN 50000
#define MAXE 800000
#define MAXET (MAXE + MAXN)

__device__ float    g_proj[MAXN * 128];     // 25.6 MB
__device__ float2   g_edge_s[MAXET];        // sorted (src bits, reduced attr)
__device__ float    g_elog[MAXET * 4];      // logits -> exp values (sorted order)
__device__ unsigned g_cnt[MAXN];            // histogram
__device__ unsigned g_tmp[MAXN];            // inclusive partial scans
__device__ unsigned g_bsum[1024];           // per-block sums
__device__ unsigned g_off[MAXN + 1];        // CSR offsets
__device__ unsigned g_cur[MAXN];            // scatter cursors
__device__ int      g_idx64;

// ---- edge-index accessor: int64 or int32, probed on device --------------------
__device__ __forceinline__ int load_idx(const void* ei, int i) {
    if (g_idx64)
        return (int)((const long long*)ei)[i];
    else
        return ((const int*)ei)[i];
}

// ================================================================================
__global__ void init_kernel(int N) {
    int i = blockIdx.x * blockDim.x + threadIdx.x;
    if (i == 0) { g_idx64 = 1; g_off[0] = 0; g_cur[0] = 0; }
    if (i < N) g_cnt[i] = 0u;
}

__global__ void detect_kernel(const long long* ei, int cnt, int N) {
    int i = blockIdx.x * blockDim.x + threadIdx.x;
    if (i >= cnt) return;
    long long v = ei[i];
    if (v < 0 || v >= (long long)N) g_idx64 = 0;
}

// histogram of dst over E edges + N self loops
__global__ void hist_kernel(const void* __restrict__ ei, int E, int N) {
    int i = blockIdx.x * blockDim.x + threadIdx.x;
    int Et = E + N;
    if (i >= Et) return;
    int dst = (i < E) ? load_idx(ei, E + i) : (i - E);
    atomicAdd(&g_cnt[dst], 1u);
}

// ---- 3-phase exclusive scan over g_cnt[0..N) ----------------------------------
__global__ void scan1_kernel(int N) {
    __shared__ unsigned s[1024];
    int i = blockIdx.x * 1024 + threadIdx.x;
    unsigned v = (i < N) ? g_cnt[i] : 0u;
    s[threadIdx.x] = v;
    __syncthreads();
#pragma unroll
    for (int d = 1; d < 1024; d <<= 1) {
        unsigned t = (threadIdx.x >= d) ? s[threadIdx.x - d] : 0u;
        __syncthreads();
        s[threadIdx.x] += t;
        __syncthreads();
    }
    if (i < N) g_tmp[i] = s[threadIdx.x];           // inclusive
    if (threadIdx.x == 1023) g_bsum[blockIdx.x] = s[1023];
}

__global__ void scan2_kernel(int nb) {
    __shared__ unsigned s[1024];
    unsigned v = (threadIdx.x < nb) ? g_bsum[threadIdx.x] : 0u;
    s[threadIdx.x] = v;
    __syncthreads();
#pragma unroll
    for (int d = 1; d < 1024; d <<= 1) {
        unsigned t = (threadIdx.x >= d) ? s[threadIdx.x - d] : 0u;
        __syncthreads();
        s[threadIdx.x] += t;
        __syncthreads();
    }
    if (threadIdx.x < nb) g_bsum[threadIdx.x] = s[threadIdx.x] - v;  // exclusive
}

__global__ void scan3_kernel(int N) {
    int i = blockIdx.x * 1024 + threadIdx.x;
    if (i >= N) return;
    unsigned incl = g_tmp[i] + g_bsum[blockIdx.x];
    g_off[i + 1] = incl;                // off[i+1] = sum cnt[0..i]
    if (i + 1 < N) g_cur[i + 1] = incl; // scatter cursor start
}

// scatter edges into dst-sorted order; payload = (src, reduced edge attr)
__global__ void scatter_kernel(const void* __restrict__ ei,
                               const float* __restrict__ ea, int E, int N) {
    int i = blockIdx.x * blockDim.x + threadIdx.x;
    int Et = E + N;
    if (i >= Et) return;
    int src, dst; float red;
    if (i < E) {
        src = load_idx(ei, i);
        dst = load_idx(ei, E + i);
        float2 e2 = ((const float2*)ea)[i];
        red = e2.x + 0.35f * e2.y;
    } else {
        src = dst = i - E;
        red = 1.0f;
    }
    unsigned pos = atomicAdd(&g_cur[dst], 1u);
    g_edge_s[pos] = make_float2(__int_as_float(src), red);
}

// ================================================================================
// Dual GEMM: grid.y==0 -> g_proj = x@W_lin^T ; grid.y==1 -> out = x@W_res^T + bias
// ================================================================================
__global__ __launch_bounds__(256, 2) void gemm_kernel(
    const float* __restrict__ x, const float* __restrict__ W_lin,
    const float* __restrict__ W_res, const float* __restrict__ bias,
    float* __restrict__ out, int N)
{
    __shared__ float xs[32][132];
    __shared__ float ws[32][132];

    const int tid = threadIdx.x;
    const int tx = tid & 15;
    const int ty = tid >> 4;
    const int rbase = blockIdx.x * 128;
    const float* W = (blockIdx.y == 0) ? W_lin : W_res;

    float acc[8][8];
#pragma unroll
    for (int i = 0; i < 8; i++)
#pragma unroll
        for (int j = 0; j < 8; j++) acc[i][j] = 0.0f;

    for (int kb = 0; kb < 128; kb += 32) {
#pragma unroll
        for (int li = tid; li < 32 * 128; li += 256) {
            int r = li >> 5;
            int k = li & 31;
            int row = rbase + r;
            xs[k][r] = (row < N) ? x[row * 128 + kb + k] : 0.0f;
            ws[k][r] = W[r * 128 + kb + k];
        }
        __syncthreads();
#pragma unroll
        for (int k = 0; k < 32; k++) {
            float a[8], b[8];
            *(float4*)&a[0] = *(const float4*)&xs[k][ty * 8];
            *(float4*)&a[4] = *(const float4*)&xs[k][ty * 8 + 4];
            *(float4*)&b[0] = *(const float4*)&ws[k][tx * 8];
            *(float4*)&b[4] = *(const float4*)&ws[k][tx * 8 + 4];
#pragma unroll
            for (int i = 0; i < 8; i++)
#pragma unroll
                for (int j = 0; j < 8; j++)
                    acc[i][j] = fmaf(a[i], b[j], acc[i][j]);
        }
        __syncthreads();
    }

    const int col = tx * 8;
#pragma unroll
    for (int i = 0; i < 8; i++) {
        int row = rbase + ty * 8 + i;
        if (row >= N) break;
        if (blockIdx.y == 0) {
            *(float4*)&g_proj[row * 128 + col]     = make_float4(acc[i][0], acc[i][1], acc[i][2], acc[i][3]);
            *(float4*)&g_proj[row * 128 + col + 4] = make_float4(acc[i][4], acc[i][5], acc[i][6], acc[i][7]);
        } else {
            float4 v0, v1;
            v0.x = acc[i][0] + bias[col + 0];
            v0.y = acc[i][1] + bias[col + 1];
            v0.z = acc[i][2] + bias[col + 2];
            v0.w = acc[i][3] + bias[col + 3];
            v1.x = acc[i][4] + bias[col + 4];
            v1.y = acc[i][5] + bias[col + 5];
            v1.z = acc[i][6] + bias[col + 6];
            v1.w = acc[i][7] + bias[col + 7];
            *(float4*)&out[row * 128 + col]     = v0;
            *(float4*)&out[row * 128 + col + 4] = v1;
        }
    }
}

// ================================================================================
// GAT node kernel: one warp per dst node. Lane covers channels 4*lane..4*lane+3,
// head h = lane>>3. Three loops over the node's incoming (sorted) edges:
//   L1: logits -> g_elog, running max (registers)
//   L2: exp, denom (registers), exp -> g_elog
//   L3: attn * proj[src] accumulated in registers; out = acc + residual
// ================================================================================
__global__ __launch_bounds__(256) void gat_node_kernel(
    const float* __restrict__ att, const float* __restrict__ W_eb,
    float* __restrict__ out, int N)
{
    int warp = (blockIdx.x * blockDim.x + threadIdx.x) >> 5;
    int lane = threadIdx.x & 31;
    if (warp >= N) return;
    const int d = warp;
    const int h = lane >> 3;

    const int beg = (int)g_off[d];
    const int end = (int)g_off[d + 1];

    const float4* p4 = (const float4*)g_proj;
    float4 pd = p4[d * 32 + lane];
    float4 a4 = ((const float4*)att)[lane];
    float web = __ldg(&W_eb[h]);

    // ---- loop 1: logits + segment max ----
    float mx = -3.4e38f;
    for (int j = beg; j < end; ++j) {
        float2 er = g_edge_s[j];
        int src = __float_as_int(er.x);
        float4 ps = p4[src * 32 + lane];
        float zx = ps.x + pd.x; zx = fmaxf(zx, 0.2f * zx);
        float zy = ps.y + pd.y; zy = fmaxf(zy, 0.2f * zy);
        float zz = ps.z + pd.z; zz = fmaxf(zz, 0.2f * zz);
        float zw = ps.w + pd.w; zw = fmaxf(zw, 0.2f * zw);
        float part = zx * a4.x + zy * a4.y + zz * a4.z + zw * a4.w;
        part += __shfl_xor_sync(0xffffffffu, part, 4);
        part += __shfl_xor_sync(0xffffffffu, part, 2);
        part += __shfl_xor_sync(0xffffffffu, part, 1);
        float logit = fmaf(er.y, web, part);
        if ((lane & 7) == 0) g_elog[j * 4 + h] = logit;
        mx = fmaxf(mx, logit);
    }
    __syncwarp();
    __threadfence_block();

    // ---- loop 2: exp + denom ----
    float den = 0.0f;
    for (int j = beg; j < end; ++j) {
        float v = expf(g_elog[j * 4 + h] - mx);
        den += v;
        if ((lane & 7) == 0) g_elog[j * 4 + h] = v;
    }
    __syncwarp();
    __threadfence_block();
    float inv = 1.0f / fmaxf(den, 1e-12f);

    // ---- loop 3: weighted aggregation ----
    float ax = 0.0f, ay = 0.0f, az = 0.0f, aw = 0.0f;
    for (int j = beg; j < end; ++j) {
        float2 er = g_edge_s[j];
        int src = __float_as_int(er.x);
        float a = g_elog[j * 4 + h] * inv;
        float4 ps = p4[src * 32 + lane];
        ax = fmaf(a, ps.x, ax);
        ay = fmaf(a, ps.y, ay);
        az = fmaf(a, ps.z, az);
        aw = fmaf(a, ps.w, aw);
    }

    float4* o4 = (float4*)out;
    float4 r = o4[d * 32 + lane];   // residual + bias from GEMM2
    r.x += ax; r.y += ay; r.z += az; r.w += aw;
    o4[d * 32 + lane] = r;
}

// ================================================================================
extern "C" void kernel_launch(void* const* d_in, const int* in_sizes, int n_in,
                              void* d_out, int out_size)
{
    const float* x     = (const float*)d_in[0];
    const void*  ei    = (const void*)d_in[1];
    const float* ea    = (const float*)d_in[2];
    const float* W_lin = (const float*)d_in[3];
    const float* att   = (const float*)d_in[4];
    const float* W_eb  = (const float*)d_in[5];
    const float* bias  = (const float*)d_in[6];
    const float* W_res = (const float*)d_in[7];
    float* out = (float*)d_out;

    int N  = in_sizes[0] / 128;
    int E  = in_sizes[1] / 2;
    int Et = E + N;
    int nb = (N + 1023) / 1024;

    init_kernel<<<(N + 255) / 256, 256>>>(N);

    int probe = (E < 65536) ? E : 65536;
    detect_kernel<<<(probe + 255) / 256, 256>>>((const long long*)ei, probe, N);

    hist_kernel<<<(Et + 255) / 256, 256>>>(ei, E, N);
    scan1_kernel<<<nb, 1024>>>(N);
    scan2_kernel<<<1, 1024>>>(nb);
    scan3_kernel<<<nb, 1024>>>(N);
    scatter_kernel<<<(Et + 255) / 256, 256>>>(ei, ea, E, N);

    gemm_kernel<<<dim3((N + 127) / 128, 2), 256>>>(x, W_lin, W_res, bias, out, N);

    gat_node_kernel<<<(N * 32 + 255) / 256, 256>>>(att, W_eb, out, N);
}

// round 3
// speedup vs baseline: 1.6841x; 1.1468x over previous
#include <cuda_runtime.h>
#include <cuda_bf16.h>

// ---------------------------------------------------------------------------
// SparseGATv2Layer, edge-sorted + online-softmax formulation.
//   1. proj = x @ W_lin^T ; res = x @ W_res^T + bias  (written to d_out)
//   2. counting-sort edges (incl. self loops) by dst
//   3. one warp per dst node: SINGLE pass over incoming edges with
//      flash-style online softmax (running max / denom / rescaled acc),
//      all state in registers, no atomics, no logits buffer.
// ---------------------------------------------------------------------------

#define MAXN 50000
#define MAXE 800000
#define MAXET (MAXE + MAXN)

__device__ float    g_proj[MAXN * 128];     // 25.6 MB
__device__ float2   g_edge_s[MAXET];        // sorted (src bits, reduced attr)
__device__ unsigned g_cnt[MAXN];            // histogram
__device__ unsigned g_tmp[MAXN];            // inclusive partial scans
__device__ unsigned g_bsum[1024];           // per-block sums
__device__ unsigned g_off[MAXN + 1];        // CSR offsets
__device__ unsigned g_cur[MAXN];            // scatter cursors
__device__ int      g_idx64;

// ---- edge-index accessor: int64 or int32, probed on device --------------------
__device__ __forceinline__ int load_idx(const void* ei, int i) {
    if (g_idx64)
        return (int)((const long long*)ei)[i];
    else
        return ((const int*)ei)[i];
}

// ================================================================================
__global__ void init_kernel(int N) {
    int i = blockIdx.x * blockDim.x + threadIdx.x;
    if (i == 0) { g_idx64 = 1; g_off[0] = 0; g_cur[0] = 0; }
    if (i < N) g_cnt[i] = 0u;
}

__global__ void detect_kernel(const long long* ei, int cnt, int N) {
    int i = blockIdx.x * blockDim.x + threadIdx.x;
    if (i >= cnt) return;
    long long v = ei[i];
    if (v < 0 || v >= (long long)N) g_idx64 = 0;
}

__global__ void hist_kernel(const void* __restrict__ ei, int E, int N) {
    int i = blockIdx.x * blockDim.x + threadIdx.x;
    int Et = E + N;
    if (i >= Et) return;
    int dst = (i < E) ? load_idx(ei, E + i) : (i - E);
    atomicAdd(&g_cnt[dst], 1u);
}

// ---- warp-shuffle block scan over g_cnt[0..N) (inclusive into g_tmp) ----------
__device__ __forceinline__ unsigned warp_incl_scan(unsigned v, int lane) {
#pragma unroll
    for (int d = 1; d < 32; d <<= 1) {
        unsigned t = __shfl_up_sync(0xffffffffu, v, d);
        if (lane >= d) v += t;
    }
    return v;
}

__global__ void scan1_kernel(int N) {
    __shared__ unsigned wsum[32];
    int i = blockIdx.x * 1024 + threadIdx.x;
    int lane = threadIdx.x & 31;
    int wid = threadIdx.x >> 5;
    unsigned v = (i < N) ? g_cnt[i] : 0u;
    unsigned incl = warp_incl_scan(v, lane);
    if (lane == 31) wsum[wid] = incl;
    __syncthreads();
    if (wid == 0) {
        unsigned w = wsum[lane];
        wsum[lane] = warp_incl_scan(w, lane) - w;   // exclusive warp prefix
    }
    __syncthreads();
    incl += wsum[wid];
    if (i < N) g_tmp[i] = incl;
    if (threadIdx.x == 1023) g_bsum[blockIdx.x] = incl;
}

__global__ void scan2_kernel(int nb) {
    __shared__ unsigned wsum[32];
    int lane = threadIdx.x & 31;
    int wid = threadIdx.x >> 5;
    unsigned v = (threadIdx.x < nb) ? g_bsum[threadIdx.x] : 0u;
    unsigned incl = warp_incl_scan(v, lane);
    if (lane == 31) wsum[wid] = incl;
    __syncthreads();
    if (wid == 0) {
        unsigned w = wsum[lane];
        wsum[lane] = warp_incl_scan(w, lane) - w;
    }
    __syncthreads();
    incl += wsum[wid];
    if (threadIdx.x < nb) g_bsum[threadIdx.x] = incl - v;  // exclusive
}

__global__ void scan3_kernel(int N) {
    int i = blockIdx.x * 1024 + threadIdx.x;
    if (i >= N) return;
    unsigned incl = g_tmp[i] + g_bsum[blockIdx.x];
    g_off[i + 1] = incl;
    if (i + 1 < N) g_cur[i + 1] = incl;
}

__global__ void scatter_kernel(const void* __restrict__ ei,
                               const float* __restrict__ ea, int E, int N) {
    int i = blockIdx.x * blockDim.x + threadIdx.x;
    int Et = E + N;
    if (i >= Et) return;
    int src, dst; float red;
    if (i < E) {
        src = load_idx(ei, i);
        dst = load_idx(ei, E + i);
        float2 e2 = ((const float2*)ea)[i];
        red = e2.x + 0.35f * e2.y;
    } else {
        src = dst = i - E;
        red = 1.0f;
    }
    unsigned pos = atomicAdd(&g_cur[dst], 1u);
    g_edge_s[pos] = make_float2(__int_as_float(src), red);
}

// ================================================================================
// Dual GEMM: grid.y==0 -> g_proj = x@W_lin^T ; grid.y==1 -> out = x@W_res^T + bias
// ================================================================================
__global__ __launch_bounds__(256, 2) void gemm_kernel(
    const float* __restrict__ x, const float* __restrict__ W_lin,
    const float* __restrict__ W_res, const float* __restrict__ bias,
    float* __restrict__ out, int N)
{
    __shared__ float xs[32][132];
    __shared__ float ws[32][132];

    const int tid = threadIdx.x;
    const int tx = tid & 15;
    const int ty = tid >> 4;
    const int rbase = blockIdx.x * 128;
    const float* W = (blockIdx.y == 0) ? W_lin : W_res;

    float acc[8][8];
#pragma unroll
    for (int i = 0; i < 8; i++)
#pragma unroll
        for (int j = 0; j < 8; j++) acc[i][j] = 0.0f;

    for (int kb = 0; kb < 128; kb += 32) {
#pragma unroll
        for (int li = tid; li < 32 * 128; li += 256) {
            int r = li >> 5;
            int k = li & 31;
            int row = rbase + r;
            xs[k][r] = (row < N) ? x[row * 128 + kb + k] : 0.0f;
            ws[k][r] = W[r * 128 + kb + k];
        }
        __syncthreads();
#pragma unroll
        for (int k = 0; k < 32; k++) {
            float a[8], b[8];
            *(float4*)&a[0] = *(const float4*)&xs[k][ty * 8];
            *(float4*)&a[4] = *(const float4*)&xs[k][ty * 8 + 4];
            *(float4*)&b[0] = *(const float4*)&ws[k][tx * 8];
            *(float4*)&b[4] = *(const float4*)&ws[k][tx * 8 + 4];
#pragma unroll
            for (int i = 0; i < 8; i++)
#pragma unroll
                for (int j = 0; j < 8; j++)
                    acc[i][j] = fmaf(a[i], b[j], acc[i][j]);
        }
        __syncthreads();
    }

    const int col = tx * 8;
#pragma unroll
    for (int i = 0; i < 8; i++) {
        int row = rbase + ty * 8 + i;
        if (row >= N) break;
        if (blockIdx.y == 0) {
            *(float4*)&g_proj[row * 128 + col]     = make_float4(acc[i][0], acc[i][1], acc[i][2], acc[i][3]);
            *(float4*)&g_proj[row * 128 + col + 4] = make_float4(acc[i][4], acc[i][5], acc[i][6], acc[i][7]);
        } else {
            float4 v0, v1;
            v0.x = acc[i][0] + bias[col + 0];
            v0.y = acc[i][1] + bias[col + 1];
            v0.z = acc[i][2] + bias[col + 2];
            v0.w = acc[i][3] + bias[col + 3];
            v1.x = acc[i][4] + bias[col + 4];
            v1.y = acc[i][5] + bias[col + 5];
            v1.z = acc[i][6] + bias[col + 6];
            v1.w = acc[i][7] + bias[col + 7];
            *(float4*)&out[row * 128 + col]     = v0;
            *(float4*)&out[row * 128 + col + 4] = v1;
        }
    }
}

// ================================================================================
// GAT node kernel, single pass with online softmax.
// One warp per dst node; lane covers channels 4*lane..4*lane+3, head h=lane>>3.
// Logit (after 8-lane shfl reduction) is uniform within each head group, so
// running max m and denominator den evolve identically across the group.
// ================================================================================
struct EdgeCalc {
    float4 ps;
    float logit;
};

__device__ __forceinline__ EdgeCalc edge_calc(float2 er, const float4* p4,
                                              float4 pd, float4 a4, float web,
                                              int lane)
{
    EdgeCalc r;
    int src = __float_as_int(er.x);
    r.ps = p4[src * 32 + lane];
    float zx = r.ps.x + pd.x; zx = fmaxf(zx, 0.2f * zx);
    float zy = r.ps.y + pd.y; zy = fmaxf(zy, 0.2f * zy);
    float zz = r.ps.z + pd.z; zz = fmaxf(zz, 0.2f * zz);
    float zw = r.ps.w + pd.w; zw = fmaxf(zw, 0.2f * zw);
    float part = zx * a4.x + zy * a4.y + zz * a4.z + zw * a4.w;
    part += __shfl_xor_sync(0xffffffffu, part, 4);
    part += __shfl_xor_sync(0xffffffffu, part, 2);
    part += __shfl_xor_sync(0xffffffffu, part, 1);
    r.logit = fmaf(er.y, web, part);
    return r;
}

__global__ __launch_bounds__(256) void gat_node_kernel(
    const float* __restrict__ att, const float* __restrict__ W_eb,
    float* __restrict__ out, int N)
{
    int warp = (blockIdx.x * blockDim.x + threadIdx.x) >> 5;
    int lane = threadIdx.x & 31;
    if (warp >= N) return;
    const int d = warp;
    const int h = lane >> 3;

    const int beg = (int)g_off[d];
    const int end = (int)g_off[d + 1];

    const float4* p4 = (const float4*)g_proj;
    float4 pd = p4[d * 32 + lane];
    float4 a4 = ((const float4*)att)[lane];
    float web = __ldg(&W_eb[h]);

    float m = -3.4e38f, den = 0.0f;
    float ax = 0.0f, ay = 0.0f, az = 0.0f, aw = 0.0f;

    int j = beg;
    // unrolled by 2: two independent gathers in flight
    for (; j + 1 < end; j += 2) {
        float2 er0 = g_edge_s[j];
        float2 er1 = g_edge_s[j + 1];
        EdgeCalc c0 = edge_calc(er0, p4, pd, a4, web, lane);
        EdgeCalc c1 = edge_calc(er1, p4, pd, a4, web, lane);

        float mnew = fmaxf(m, fmaxf(c0.logit, c1.logit));
        float s  = __expf(m - mnew);
        float p0 = __expf(c0.logit - mnew);
        float p1 = __expf(c1.logit - mnew);
        den = fmaf(den, s, p0 + p1);
        ax = fmaf(ax, s, fmaf(p0, c0.ps.x, p1 * c1.ps.x));
        ay = fmaf(ay, s, fmaf(p0, c0.ps.y, p1 * c1.ps.y));
        az = fmaf(az, s, fmaf(p0, c0.ps.z, p1 * c1.ps.z));
        aw = fmaf(aw, s, fmaf(p0, c0.ps.w, p1 * c1.ps.w));
        m = mnew;
    }
    if (j < end) {
        float2 er0 = g_edge_s[j];
        EdgeCalc c0 = edge_calc(er0, p4, pd, a4, web, lane);
        float mnew = fmaxf(m, c0.logit);
        float s = __expf(m - mnew);
        float p0 = __expf(c0.logit - mnew);
        den = fmaf(den, s, p0);
        ax = fmaf(ax, s, p0 * c0.ps.x);
        ay = fmaf(ay, s, p0 * c0.ps.y);
        az = fmaf(az, s, p0 * c0.ps.z);
        aw = fmaf(aw, s, p0 * c0.ps.w);
        m = mnew;
    }

    float inv = 1.0f / fmaxf(den, 1e-12f);
    float4* o4 = (float4*)out;
    float4 r = o4[d * 32 + lane];   // residual + bias from GEMM2
    r.x = fmaf(ax, inv, r.x);
    r.y = fmaf(ay, inv, r.y);
    r.z = fmaf(az, inv, r.z);
    r.w = fmaf(aw, inv, r.w);
    o4[d * 32 + lane] = r;
}

// ================================================================================
extern "C" void kernel_launch(void* const* d_in, const int* in_sizes, int n_in,
                              void* d_out, int out_size)
{
    const float* x     = (const float*)d_in[0];
    const void*  ei    = (const void*)d_in[1];
    const float* ea    = (const float*)d_in[2];
    const float* W_lin = (const float*)d_in[3];
    const float* att   = (const float*)d_in[4];
    const float* W_eb  = (const float*)d_in[5];
    const float* bias  = (const float*)d_in[6];
    const float* W_res = (const float*)d_in[7];
    float* out = (float*)d_out;

    int N  = in_sizes[0] / 128;
    int E  = in_sizes[1] / 2;
    int Et = E + N;
    int nb = (N + 1023) / 1024;

    init_kernel<<<(N + 255) / 256, 256>>>(N);

    int probe = (E < 65536) ? E : 65536;
    detect_kernel<<<(probe + 255) / 256, 256>>>((const long long*)ei, probe, N);

    hist_kernel<<<(Et + 255) / 256, 256>>>(ei, E, N);
    scan1_kernel<<<nb, 1024>>>(N);
    scan2_kernel<<<1, 1024>>>(nb);
    scan3_kernel<<<nb, 1024>>>(N);
    scatter_kernel<<<(Et + 255) / 256, 256>>>(ei, ea, E, N);

    gemm_kernel<<<dim3((N + 127) / 128, 2), 256>>>(x, W_lin, W_res, bias, out, N);

    gat_node_kernel<<<(N * 32 + 255) / 256, 256>>>(att, W_eb, out, N);
}